// round 1
// baseline (speedup 1.0000x reference)
#include <cuda_runtime.h>

#define NBOX   8192
#define NT     1024
#define NWORDS (NBOX / 64)
#define ROWS   (NBOX / NT)   // 8 elements per thread

struct SmemLayout {
    unsigned long long keys[NBOX];     // (conf_bits<<32) | (0xFFFFFFFF - idx), sorted descending
    float4             boxes[NBOX];    // xyxy, filled for i < V
    unsigned long long keep[NWORDS];   // keep bitmask over sorted order
    float              redbuf[32];
    float              maxv;
    int                V;
    int                cur;
};

__global__ void __launch_bounds__(NT, 1)
rtdetr_postprocess_kernel(const float* __restrict__ in, float* __restrict__ out)
{
    extern __shared__ unsigned char smem_raw[];
    SmemLayout* s = reinterpret_cast<SmemLayout*>(smem_raw);
    const int tid = threadIdx.x;

    // ---- 1. load conf, block max reduce ----
    float confs[ROWS];
    float lmax = 0.0f;  // conf values are uniform[0,1) -> non-negative
#pragma unroll
    for (int r = 0; r < ROWS; r++) {
        int i = tid + r * NT;
        float c = in[i * 5 + 4];
        confs[r] = c;
        lmax = fmaxf(lmax, c);
    }
#pragma unroll
    for (int o = 16; o > 0; o >>= 1) lmax = fmaxf(lmax, __shfl_xor_sync(0xFFFFFFFFu, lmax, o));
    if ((tid & 31) == 0) s->redbuf[tid >> 5] = lmax;
    __syncthreads();
    if (tid < 32) {
        float v = s->redbuf[tid];
#pragma unroll
        for (int o = 16; o > 0; o >>= 1) v = fmaxf(v, __shfl_xor_sync(0xFFFFFFFFu, v, o));
        if (tid == 0) s->maxv = v;
    }

    // ---- build sort keys: descending conf, stable (ascending original index on ties) ----
#pragma unroll
    for (int r = 0; r < ROWS; r++) {
        int i = tid + r * NT;
        unsigned int cb = __float_as_uint(confs[r]);  // non-negative floats: bit pattern is order-preserving
        s->keys[i] = ((unsigned long long)cb << 32) | (unsigned int)(0xFFFFFFFFu - (unsigned int)i);
    }
    __syncthreads();

    // ---- 2. bitonic sort, descending ----
    for (int k = 2; k <= NBOX; k <<= 1) {
        for (int j = k >> 1; j > 0; j >>= 1) {
#pragma unroll
            for (int r = 0; r < ROWS; r++) {
                int i = tid + r * NT;
                int ixj = i ^ j;
                if (ixj > i) {
                    unsigned long long a = s->keys[i];
                    unsigned long long b = s->keys[ixj];
                    bool desc = ((i & k) == 0);
                    if (desc ? (a < b) : (a > b)) {
                        s->keys[i]   = b;
                        s->keys[ixj] = a;
                    }
                }
            }
            __syncthreads();
        }
    }

    // ---- 3. V = length of valid prefix (score >= 0.5 after normalization) ----
    const float maxv = s->maxv;
#pragma unroll
    for (int r = 0; r < ROWS; r++) {
        int i = tid + r * NT;
        float c = __uint_as_float((unsigned int)(s->keys[i] >> 32));
        bool v = (c / maxv) >= 0.5f;
        bool vprev = true;
        if (i > 0) {
            float cp = __uint_as_float((unsigned int)(s->keys[i - 1] >> 32));
            vprev = (cp / maxv) >= 0.5f;
        }
        if (!v && vprev) s->V = i;             // first invalid
        if (i == NBOX - 1 && v) s->V = NBOX;   // all valid
    }
    __syncthreads();
    const int V = s->V;

    // ---- 4. gather xyxy boxes for the valid prefix; init keep bitmask ----
    for (int i = tid; i < V; i += NT) {
        unsigned int idx = 0xFFFFFFFFu - (unsigned int)(s->keys[i] & 0xFFFFFFFFull);
        const float* p = in + (size_t)idx * 5;
        float cx = p[0], cy = p[1], w = p[2], h = p[3];
        s->boxes[i] = make_float4(cx - w * 0.5f, cy - h * 0.5f,
                                  cx + w * 0.5f, cy + h * 0.5f);
    }
    for (int wI = tid; wI < NWORDS; wI += NT) {
        int base = wI * 64;
        unsigned long long word;
        if (V >= base + 64)      word = ~0ull;
        else if (V <= base)      word = 0ull;
        else                     word = (1ull << (V - base)) - 1ull;
        s->keep[wI] = word;
    }
    __syncthreads();

    // ---- 5. greedy NMS over sorted order ----
    int scan_pos = 0;  // meaningful on thread 0 only
    while (true) {
        if (tid == 0) {
            int found = -1;
            while (scan_pos < V) {
                int w = scan_pos >> 6;
                unsigned long long word = s->keep[w] >> (scan_pos & 63);
                if (word == 0ull) { scan_pos = (w + 1) << 6; continue; }
                found = scan_pos + (__ffsll((long long)word) - 1);
                scan_pos = found + 1;
                break;
            }
            s->cur = found;
        }
        __syncthreads();
        int i = s->cur;
        if (i < 0) break;

        float4 bi = s->boxes[i];
        float areai = (bi.z - bi.x) * (bi.w - bi.y);
        for (int j = i + 1 + tid; j < V; j += NT) {
            float4 bj = s->boxes[j];
            float ix1 = fmaxf(bi.x, bj.x);
            float iy1 = fmaxf(bi.y, bj.y);
            float ix2 = fminf(bi.z, bj.z);
            float iy2 = fminf(bi.w, bj.w);
            float iw  = fmaxf(ix2 - ix1, 0.0f);
            float ih  = fmaxf(iy2 - iy1, 0.0f);
            float inter = iw * ih;
            float areaj = (bj.z - bj.x) * (bj.w - bj.y);
            float uni   = areai + areaj - inter;
            float iou   = inter / fmaxf(uni, 1e-9f);
            if (iou > 0.5f)
                atomicAnd(&s->keep[j >> 6], ~(1ull << (j & 63)));
        }
        __syncthreads();
    }

    // ---- 6. output: kept rows get [xyxy, score], everything else zeros ----
#pragma unroll
    for (int r = 0; r < ROWS; r++) {
        int i = tid + r * NT;
        bool kept = (i < V) && ((s->keep[i >> 6] >> (i & 63)) & 1ull);
        float o0 = 0.f, o1 = 0.f, o2 = 0.f, o3 = 0.f, o4 = 0.f;
        if (kept) {
            float4 b = s->boxes[i];
            float c  = __uint_as_float((unsigned int)(s->keys[i] >> 32));
            o0 = b.x; o1 = b.y; o2 = b.z; o3 = b.w; o4 = c / maxv;
        }
        out[i * 5 + 0] = o0;
        out[i * 5 + 1] = o1;
        out[i * 5 + 2] = o2;
        out[i * 5 + 3] = o3;
        out[i * 5 + 4] = o4;
    }
}

extern "C" void kernel_launch(void* const* d_in, const int* in_sizes, int n_in,
                              void* d_out, int out_size)
{
    (void)in_sizes; (void)n_in; (void)out_size;
    const float* in = (const float*)d_in[0];
    float* out = (float*)d_out;

    const int smem_bytes = (int)sizeof(SmemLayout);
    cudaFuncSetAttribute(rtdetr_postprocess_kernel,
                         cudaFuncAttributeMaxDynamicSharedMemorySize, smem_bytes);
    rtdetr_postprocess_kernel<<<1, NT, smem_bytes>>>(in, out);
}